// round 3
// baseline (speedup 1.0000x reference)
#include <cuda_runtime.h>
#include <cuda_bf16.h>

// Problem constants
#define NN        64
#define MM        2080          // N*(N+1)/2
#define NWORDS    65            // 2080 / 32 exactly
#define TOPK      5
#define NEIGHBOR  16
#define NEGATIVE  16
#define TOTAL     85            // TOPK*(NEIGHBOR+1)
#define KOUT      101           // NEGATIVE + TOTAL
#define BB        32
#define DD        512
#define SORTN     4096
#define THR       256

// Output layout: concat(prop_feature, pred_s_e, offset_sel, pred_score) as f32
#define BK        (BB*KOUT)     // 3232
#define F1        (BK*DD)       // 1654784
#define F2        (F1 + BK*2)   // 1661248
#define F3        (F2 + BK*2)   // 1667712

__device__ int g_sel_m[BK];     // selected original proposal index per (b,k)

// T(r) = number of upper-tri entries in rows < r = r*(129-r)/2
__device__ __forceinline__ int tri_base(int r) { return r * (129 - r) / 2; }

__global__ __launch_bounds__(THR)
void select_kernel(const float* __restrict__ score_pred)
{
    __shared__ unsigned long long keys[SORTN];
    __shared__ unsigned char rtab[MM], ctab[MM];
    __shared__ unsigned int sup[NWORDS], selb[NWORDS];

    const int b   = blockIdx.x;
    const int tid = threadIdx.x;

    // Build (row, col) lookup tables for upper-tri row-major enumeration
    if (tid < NN) {
        int r = tid;
        int base = tri_base(r);
        for (int c = r; c < NN; c++) {
            rtab[base + c - r] = (unsigned char)r;
            ctab[base + c - r] = (unsigned char)c;
        }
    }
    for (int w = tid; w < NWORDS; w += THR) { sup[w] = 0u; selb[w] = 0u; }
    __syncthreads();

    // Pack sort keys: hi = order-inverted float bits (descending score),
    // lo = original index (stable tie-break, identical to stable argsort(-s)).
    const float* sp = score_pred + (size_t)b * NN * NN;
    for (int m = tid; m < SORTN; m += THR) {
        if (m < MM) {
            int r = rtab[m], c = ctab[m];
            unsigned u  = __float_as_uint(sp[r * NN + c]);
            unsigned sa = (u & 0x80000000u) ? ~u : (u | 0x80000000u);  // ascending-sortable
            unsigned hi = ~sa;                                         // descending key
            keys[m] = ((unsigned long long)hi << 32) | (unsigned)m;
        } else {
            keys[m] = 0xFFFFFFFFFFFFFFFFULL;   // pad: sorts to the end
        }
    }
    __syncthreads();

    // Bitonic sort, ascending on u64 key
    for (int k = 2; k <= SORTN; k <<= 1) {
        for (int j = k >> 1; j > 0; j >>= 1) {
            for (int i = tid; i < SORTN; i += THR) {
                int ixj = i ^ j;
                if (ixj > i) {
                    unsigned long long a = keys[i], c2 = keys[ixj];
                    bool up = ((i & k) == 0);
                    if ((a > c2) == up) { keys[i] = c2; keys[ixj] = a; }
                }
            }
            __syncthreads();
        }
    }

    // Greedy selection on warp 0. Only unsuppressed i does work -> <= TOPK heavy iters.
    if (tid < 32) {
        const int lane = tid;
        const unsigned lt = (1u << lane) - 1u;   // lanemask_lt (lane=0 -> 0)

        int i = 0, cnt = 0;
        while (cnt < TOPK && i < MM - 1) {
            bool supi = (sup[i >> 5] >> (i & 31)) & 1u;
            if (!supi) {
                int mi = (int)(keys[i] & 0xFFFFFFFFu);
                int s0 = rtab[mi], e0 = (int)ctab[mi] + 1;
                int count = 0;
                for (int w = 0; w < NWORDS; w++) {
                    int pos = (w << 5) + lane;            // pos < 2080 always (65*32)
                    bool mbit = false;
                    if (pos > i) {
                        int mj = (int)(keys[pos] & 0xFFFFFFFFu);
                        int s1 = rtab[mj], e1 = (int)ctab[mj] + 1;
                        int inter = min(e1, e0) - max(s1, s0);
                        int uni   = max(e1, e0) - min(s1, s0);
                        // iou > 0.5  <=>  2*inter > union (exact integer form)
                        mbit = (inter > 0) && (2 * inter > uni);
                    }
                    unsigned mk = __ballot_sync(0xFFFFFFFFu, mbit);
                    int rank = count + __popc(mk & lt);        // exclusive cumsum
                    bool nbbit = mbit && (rank < NEIGHBOR);    // cumsum(mask) <= 16
                    unsigned nbm = __ballot_sync(0xFFFFFFFFu, nbbit);
                    if (lane == 0) { sup[w] |= mk; selb[w] |= nbm; }
                    count += __popc(mk);
                }
                if (lane == 0) {
                    sup[i >> 5]  |= 1u << (i & 31);
                    selb[i >> 5] |= 1u << (i & 31);
                }
                cnt++;
                __syncwarp();
            }
            i++;
        }

        // Index assembly on one thread (cheap: ~2*2080 bit tests)
        if (lane == 0) {
            int n_unsup = 0, n_sel = 0;
            for (int w = 0; w < NWORDS; w++) {
                n_unsup += __popc(~sup[w]);
                n_sel   += __popc(selb[w]);
            }
            int pad = TOTAL - n_sel;   // n_sel <= 85 structurally
            int mid[TOTAL];
            int neg[NEGATIVE];
            for (int p = 0; p < TOTAL; p++) mid[p] = MM - 1;   // fill value
            int first_unsup = MM - 1;                          // unsup_idx[0] fill
            int cu = 0;
            int cs = 0;
            for (int pos = 0; pos < MM; pos++) {
                unsigned bit = 1u << (pos & 31);
                bool u  = !(sup[pos >> 5] & bit);
                bool sl = (selb[pos >> 5] & bit) != 0;
                if (u) {
                    if (cu == 0) first_unsup = pos;
                    if (cu < pad) mid[cu] = pos;               // top unsuppressed padding
                    int back = n_unsup - 1 - cu;               // reversed tail position
                    if (back < NEGATIVE) neg[back] = pos;      // last 16 unsuppressed
                    cu++;
                }
                if (sl) { mid[pad + cs] = pos; cs++; }         // pad+cs < 85 structurally
            }
            // clip(n_unsup-1-j, 0, M-1): for j >= n_unsup -> unsup_idx[0]
            for (int j = n_unsup; j < NEGATIVE; j++) neg[j] = first_unsup;

            int ob = b * KOUT;
            for (int k2 = 0; k2 < KOUT; k2++) {
                int pos = (k2 < NEGATIVE) ? neg[k2] : mid[k2 - NEGATIVE];
                g_sel_m[ob + k2] = (int)(keys[pos] & 0xFFFFFFFFu);  // order[idx_sorted]
            }
        }
    }
}

__global__ __launch_bounds__(128)
void gather_kernel(const float* __restrict__ map2d,
                   const float* __restrict__ offset_gt,
                   const float* __restrict__ tmap,
                   float* __restrict__ out)
{
    const int k = blockIdx.x;          // 0..3231
    const int b = k / KOUT;
    const int m = g_sel_m[k];

    // invert triangular enumeration: largest r with tri_base(r) <= m
    int lo = 0, hi = NN - 1;
    while (lo < hi) {
        int md = (lo + hi + 1) >> 1;
        if (tri_base(md) <= m) lo = md; else hi = md - 1;
    }
    const int r = lo;
    const int c = r + (m - tri_base(r));

    const size_t cell = ((size_t)b * NN + r) * NN + c;
    const float4* src = (const float4*)(map2d + cell * DD);
    float4*       dst = (float4*)(out + (size_t)k * DD);
    dst[threadIdx.x] = src[threadIdx.x];   // 128 threads * float4 = 512 floats

    if (threadIdx.x == 0) {
        out[F1 + 2 * k]     = (float)r;
        out[F1 + 2 * k + 1] = (float)(c + 1);
        out[F2 + 2 * k]     = offset_gt[cell * 2];
        out[F2 + 2 * k + 1] = offset_gt[cell * 2 + 1];
        out[F3 + k]         = tmap[cell];
    }
}

extern "C" void kernel_launch(void* const* d_in, const int* in_sizes, int n_in,
                              void* d_out, int out_size)
{
    // Inputs: score_pred, map2d_mask(bool, ignored), map2d, offset_gt, tmap
    const float* score = (const float*)d_in[0];
    int o = (n_in >= 5) ? 1 : 0;   // skip the mask input if present
    const float* map2d  = (const float*)d_in[1 + o];
    const float* offg   = (const float*)d_in[2 + o];
    const float* tm     = (const float*)d_in[3 + o];
    float* out = (float*)d_out;

    select_kernel<<<BB, THR>>>(score);
    gather_kernel<<<BK, 128>>>(map2d, offg, tm, out);
}

// round 4
// speedup vs baseline: 1.3210x; 1.3210x over previous
#include <cuda_runtime.h>
#include <cuda_bf16.h>

// Problem constants
#define NN        64
#define MM        2080          // N*(N+1)/2
#define NWORDS    65            // 2080 / 32 exactly (no partial word)
#define TOPK      5
#define NEIGHBOR  16
#define NEGATIVE  16
#define TOTAL     85            // TOPK*(NEIGHBOR+1)
#define KOUT      101           // NEGATIVE + TOTAL
#define BB        32
#define DD        512
#define SORTN     4096
#define THR       1024

// Output layout: concat(prop_feature, pred_s_e, offset_sel, pred_score) as f32
#define BK        (BB*KOUT)     // 3232
#define F1        (BK*DD)       // 1654784
#define F2        (F1 + BK*2)   // 1661248
#define F3        (F2 + BK*2)   // 1667712

__device__ int g_sel_m[BK];     // selected original proposal index per (b,k)

__device__ __forceinline__ int tri_base(int r) { return r * (129 - r) / 2; }

__device__ __forceinline__ void cswap(unsigned long long& a, unsigned long long& b, bool up)
{
    if ((a > b) == up) { unsigned long long t = a; a = b; b = t; }
}

__global__ __launch_bounds__(THR)
void select_kernel(const float* __restrict__ score_pred)
{
    __shared__ unsigned long long keys[SORTN];
    __shared__ unsigned char rtab[MM], ctab[MM];
    __shared__ unsigned short se[MM];            // packed (s | e<<8) per sorted pos
    __shared__ unsigned int sup[NWORDS], selb[NWORDS], tmpm[NWORDS];
    __shared__ int Pun[NWORDS], Psel[NWORDS];
    __shared__ int midpos[TOTAL], negpos[NEGATIVE];
    __shared__ int s_nunsup, s_pad, s_first;

    const int b    = blockIdx.x;
    const int tid  = threadIdx.x;
    const int lane = tid & 31;
    const int wv   = tid >> 5;   // warp id in block (0..31)

    // ---- Build (row,col) tables for upper-tri row-major enumeration ----
    if (tid < NN) {
        int r = tid;
        int base = tri_base(r);
        for (int c = r; c < NN; c++) {
            rtab[base + c - r] = (unsigned char)r;
            ctab[base + c - r] = (unsigned char)c;
        }
    }
    if (tid < NWORDS) { sup[tid] = 0u; selb[tid] = 0u; }
    if (tid < TOTAL)    midpos[tid] = MM - 1;
    if (tid < NEGATIVE) negpos[tid] = MM - 1;
    if (tid == 0) s_first = MM - 1;
    __syncthreads();

    // ---- Pack sort keys: hi = descending-order float bits, lo = index (stable) ----
    const float* sp = score_pred + (size_t)b * NN * NN;
    #pragma unroll
    for (int m = tid; m < SORTN; m += THR) {
        if (m < MM) {
            int r = rtab[m], c = ctab[m];
            unsigned u  = __float_as_uint(sp[r * NN + c]);
            unsigned sa = (u & 0x80000000u) ? ~u : (u | 0x80000000u);
            unsigned hi = ~sa;
            keys[m] = ((unsigned long long)hi << 32) | (unsigned)m;
        } else {
            keys[m] = 0xFFFFFFFFFFFFFFFFULL;
        }
    }
    __syncthreads();

    // ---- Bitonic sort (ascending). j>=4 via SMEM, j=2,1 fused in registers ----
    const int i0 = tid * 4;
    for (int k = 2; k <= SORTN; k <<= 1) {
        for (int j = k >> 1; j >= 4; j >>= 1) {
            #pragma unroll
            for (int t = tid; t < SORTN; t += THR) {
                int ixj = t ^ j;
                if (ixj > t) {
                    unsigned long long a = keys[t], c2 = keys[ixj];
                    bool up = ((t & k) == 0);
                    if ((a > c2) == up) { keys[t] = c2; keys[ixj] = a; }
                }
            }
            __syncthreads();
        }
        // fused register stage for j=2 (if k>2) and j=1 on contiguous quad [i0..i0+3]
        {
            unsigned long long e0 = keys[i0], e1 = keys[i0+1], e2 = keys[i0+2], e3 = keys[i0+3];
            bool upA = ((i0 & k) == 0);
            if (k > 2) {
                // j=2: up identical across the quad (k>=4)
                cswap(e0, e2, upA); cswap(e1, e3, upA);
                cswap(e0, e1, upA); cswap(e2, e3, upA);
            } else {
                bool upB = (((i0 + 2) & k) == 0);   // k=2: upA=true, upB=false
                cswap(e0, e1, upA); cswap(e2, e3, upB);
            }
            keys[i0] = e0; keys[i0+1] = e1; keys[i0+2] = e2; keys[i0+3] = e3;
            __syncthreads();
        }
    }

    // ---- Precompute packed (s,e) per sorted position ----
    #pragma unroll
    for (int p = tid; p < MM; p += THR) {
        int m = (int)(keys[p] & 0xFFFFFFFFu);
        se[p] = (unsigned short)((int)rtab[m] | (((int)ctab[m] + 1) << 8));
    }
    __syncthreads();

    // ---- Greedy selection: block-parallel mask compute, <= TOPK heavy iters ----
    {
        int i = 0, cnt = 0;
        while (cnt < TOPK && i < MM - 1) {
            if ((sup[i >> 5] >> (i & 31)) & 1u) { i++; continue; }   // uniform skip
            int se0 = se[i];
            int s0 = se0 & 0xFF, e0 = se0 >> 8;

            // compute IoU mask bits for all 2080 positions; ballots -> word masks
            #pragma unroll
            for (int c = 0; c < 3; c++) {
                int pos = c * 1024 + tid;
                bool mbit = false;
                if (pos < MM && pos > i) {
                    int se1 = se[pos];
                    int s1 = se1 & 0xFF, e1 = se1 >> 8;
                    int inter = min(e1, e0) - max(s1, s0);
                    int uni   = max(e1, e0) - min(s1, s0);
                    mbit = (inter > 0) && (2 * inter > uni);   // iou > 0.5 exact
                }
                unsigned mk = __ballot_sync(0xFFFFFFFFu, mbit);
                int wix = c * 32 + wv;
                if (lane == 0 && wix < NWORDS) tmpm[wix] = mk;
            }
            __syncthreads();

            // serial prefix pass over 65 words: neighbor cutoff + OR into state
            if (tid == 0) {
                int count = 0;
                for (int w = 0; w < NWORDS; w++) {
                    unsigned mk = tmpm[w];
                    int pc = __popc(mk);
                    unsigned nbm;
                    if (count >= NEIGHBOR)            nbm = 0u;
                    else if (count + pc <= NEIGHBOR)  nbm = mk;
                    else {
                        int keep = NEIGHBOR - count;
                        unsigned t2 = mk;
                        while (__popc(t2) > keep)     // drop highest set bits
                            t2 ^= (0x80000000u >> __clz(t2));
                        nbm = t2;
                    }
                    sup[w]  |= mk;
                    selb[w] |= nbm;
                    count += pc;
                }
                sup[i >> 5]  |= 1u << (i & 31);
                selb[i >> 5] |= 1u << (i & 31);
            }
            __syncthreads();
            cnt++; i++;
        }
    }
    __syncthreads();

    // ---- Word-level exclusive prefix counts (serial over 65 words, cheap) ----
    if (tid == 0) {
        int au = 0, as2 = 0;
        for (int w = 0; w < NWORDS; w++) {
            Pun[w]  = au;  au  += __popc(~sup[w]);
            Psel[w] = as2; as2 += __popc(selb[w]);
        }
        s_nunsup = au;
        s_pad    = TOTAL - as2;     // n_sel <= 85 structurally
    }
    __syncthreads();

    // ---- Parallel emit of neg/mid position lists by rank ----
    if (tid < NWORDS) {
        const int w = tid;
        const int pad = s_pad, nun = s_nunsup;
        unsigned un = ~sup[w];
        int rank = Pun[w];
        while (un) {
            int bp = __ffs(un) - 1; un &= un - 1;
            int pos = (w << 5) + bp;
            if (rank == 0) s_first = pos;
            if (rank < pad) midpos[rank] = pos;               // top-unsup padding
            int back = nun - 1 - rank;                        // reversed tail
            if (back >= 0 && back < NEGATIVE) negpos[back] = pos;
            rank++;
        }
        unsigned sl = selb[w];
        int rs = Psel[w];
        while (sl) {
            int bp = __ffs(sl) - 1; sl &= sl - 1;
            int pos = (w << 5) + bp;
            int slot = pad + rs;
            if (slot < TOTAL) midpos[slot] = pos;
            rs++;
        }
    }
    __syncthreads();
    // clip(n_unsup-1-j, 0, ...): j >= n_unsup -> unsup_idx[0] (or fill)
    if (tid < NEGATIVE && tid >= s_nunsup) negpos[tid] = s_first;
    __syncthreads();

    if (tid < KOUT) {
        int pos = (tid < NEGATIVE) ? negpos[tid] : midpos[tid - NEGATIVE];
        g_sel_m[b * KOUT + tid] = (int)(keys[pos] & 0xFFFFFFFFu);
    }
}

__global__ __launch_bounds__(128)
void gather_kernel(const float* __restrict__ map2d,
                   const float* __restrict__ offset_gt,
                   const float* __restrict__ tmap,
                   float* __restrict__ out)
{
    const int k = blockIdx.x;          // 0..3231
    const int b = k / KOUT;
    const int m = g_sel_m[k];

    // invert triangular enumeration: largest r with tri_base(r) <= m
    int lo = 0, hi = NN - 1;
    while (lo < hi) {
        int md = (lo + hi + 1) >> 1;
        if (tri_base(md) <= m) lo = md; else hi = md - 1;
    }
    const int r = lo;
    const int c = r + (m - tri_base(r));

    const size_t cell = ((size_t)b * NN + r) * NN + c;
    const float4* src = (const float4*)(map2d + cell * DD);
    float4*       dst = (float4*)(out + (size_t)k * DD);
    dst[threadIdx.x] = src[threadIdx.x];   // 128 threads * float4 = 512 floats

    if (threadIdx.x == 0) {
        out[F1 + 2 * k]     = (float)r;
        out[F1 + 2 * k + 1] = (float)(c + 1);
        out[F2 + 2 * k]     = offset_gt[cell * 2];
        out[F2 + 2 * k + 1] = offset_gt[cell * 2 + 1];
        out[F3 + k]         = tmap[cell];
    }
}

extern "C" void kernel_launch(void* const* d_in, const int* in_sizes, int n_in,
                              void* d_out, int out_size)
{
    // Inputs: score_pred, map2d_mask(bool, ignored), map2d, offset_gt, tmap
    const float* score = (const float*)d_in[0];
    int o = (n_in >= 5) ? 1 : 0;   // skip the mask input if present
    const float* map2d  = (const float*)d_in[1 + o];
    const float* offg   = (const float*)d_in[2 + o];
    const float* tm     = (const float*)d_in[3 + o];
    float* out = (float*)d_out;

    select_kernel<<<BB, THR>>>(score);
    gather_kernel<<<BK, 128>>>(map2d, offg, tm, out);
}

// round 5
// speedup vs baseline: 3.0452x; 2.3052x over previous
#include <cuda_runtime.h>
#include <cuda_bf16.h>

// Problem constants
#define NN        64
#define MM        2080          // N*(N+1)/2
#define NWORDS    65            // 2080 / 32 exactly (no partial word)
#define TOPK      5
#define NEIGHBOR  16
#define NEGATIVE  16
#define TOTAL     85            // TOPK*(NEIGHBOR+1)
#define KOUT      101           // NEGATIVE + TOTAL
#define BB        32
#define DD        512
#define SORTN     4096
#define THR       1024

// Output layout: concat(prop_feature, pred_s_e, offset_sel, pred_score) as f32
#define BK        (BB*KOUT)     // 3232
#define F1        (BK*DD)       // 1654784
#define F2        (F1 + BK*2)   // 1661248
#define F3        (F2 + BK*2)   // 1667712

__device__ int g_sel_m[BK];     // selected original proposal index per (b,k)

__device__ __forceinline__ int tri_base(int r) { return r * (129 - r) / 2; }

__device__ __forceinline__ void cswap(unsigned long long& a, unsigned long long& b, bool up)
{
    if ((a > b) == up) { unsigned long long t = a; a = b; b = t; }
}

// One bitonic exchange stage for j in {4..64} over 4 register-resident elements.
// Element index of v[r] is e0 + r; partner is e ^ j, which lives in lane ^ (j>>2).
__device__ __forceinline__ void stage_shfl(unsigned long long v[4], int e0, int j, int k)
{
    #pragma unroll
    for (int r = 0; r < 4; r++) {
        unsigned long long other = __shfl_xor_sync(0xFFFFFFFFu, v[r], j >> 2);
        int e = e0 + r;
        bool lower    = ((e & j) == 0);
        bool up       = ((e & k) == 0);
        bool take_min = (lower == up);
        bool mine_lt  = (v[r] < other);
        v[r] = (mine_lt == take_min) ? v[r] : other;
    }
}

// Warp-local tail for k >= 256: stages j = 64..4 (shuffle) then j = 2,1 (register).
__device__ __forceinline__ void warp_tail(unsigned long long v[4], int e0, int k)
{
    #pragma unroll
    for (int j = 64; j >= 4; j >>= 1) stage_shfl(v, e0, j, k);
    bool up = ((e0 & k) == 0);           // k >= 256: same for all 4 elements
    cswap(v[0], v[2], up); cswap(v[1], v[3], up);
    cswap(v[0], v[1], up); cswap(v[2], v[3], up);
}

__global__ __launch_bounds__(THR)
void select_kernel(const float* __restrict__ score_pred)
{
    __shared__ unsigned long long keys[SORTN];
    __shared__ unsigned char rtab[MM], ctab[MM];
    __shared__ unsigned short se[MM];            // packed (s | e<<8) per sorted pos
    __shared__ unsigned int sup[NWORDS], selb[NWORDS], tmpm[NWORDS];
    __shared__ int Pun[NWORDS], Psel[NWORDS];
    __shared__ int midpos[TOTAL], negpos[NEGATIVE];
    __shared__ int s_nunsup, s_pad, s_first;

    const int b    = blockIdx.x;
    const int tid  = threadIdx.x;
    const int lane = tid & 31;
    const int wv   = tid >> 5;   // warp id in block (0..31)
    const int e0   = tid * 4;    // this thread's 4 contiguous logical elements

    // ---- Build (row,col) tables for upper-tri row-major enumeration ----
    if (tid < NN) {
        int r = tid;
        int base = tri_base(r);
        for (int c = r; c < NN; c++) {
            rtab[base + c - r] = (unsigned char)r;
            ctab[base + c - r] = (unsigned char)c;
        }
    }
    if (tid < NWORDS) { sup[tid] = 0u; selb[tid] = 0u; }
    if (tid < TOTAL)    midpos[tid] = MM - 1;
    if (tid < NEGATIVE) negpos[tid] = MM - 1;
    if (tid == 0) s_first = MM - 1;
    __syncthreads();

    // ---- Pack sort keys DIRECTLY into registers ----
    // hi = descending-order float bits, lo = index (stable argsort(-s) semantics)
    const float* sp = score_pred + (size_t)b * NN * NN;
    unsigned long long v[4];
    #pragma unroll
    for (int r4 = 0; r4 < 4; r4++) {
        int m = e0 + r4;
        if (m < MM) {
            int r = rtab[m], c = ctab[m];
            unsigned u  = __float_as_uint(sp[r * NN + c]);
            unsigned sa = (u & 0x80000000u) ? ~u : (u | 0x80000000u);
            unsigned hi = ~sa;
            v[r4] = ((unsigned long long)hi << 32) | (unsigned)m;
        } else {
            v[r4] = 0xFFFFFFFFFFFFFFFFULL;   // pad: sorts to the end
        }
    }

    // ---- Phase A: k = 2..128, entirely warp-local (NO barriers, NO smem) ----
    #pragma unroll
    for (int k = 2; k <= 128; k <<= 1) {
        #pragma unroll
        for (int j = k >> 1; j >= 4; j >>= 1) stage_shfl(v, e0, j, k);
        if (k >= 4) {                       // j=2 stage: up same for all 4 elems
            bool up = ((e0 & k) == 0);
            cswap(v[0], v[2], up); cswap(v[1], v[3], up);
        }
        {                                   // j=1 stage
            bool upA = ((e0 & k) == 0);
            bool upB = (((e0 + 2) & k) == 0);
            cswap(v[0], v[1], upA); cswap(v[2], v[3], upB);
        }
    }
    #pragma unroll
    for (int r4 = 0; r4 < 4; r4++) keys[e0 + r4] = v[r4];
    __syncthreads();

    // ---- Phases k = 256..4096: SMEM stages for j>=128, warp-local tail ----
    for (int k = 256; k <= SORTN; k <<= 1) {
        for (int j = k >> 1; j >= 128; j >>= 1) {
            #pragma unroll
            for (int t = tid; t < SORTN; t += THR) {
                int ixj = t ^ j;
                if (ixj > t) {
                    unsigned long long a = keys[t], c2 = keys[ixj];
                    bool up = ((t & k) == 0);
                    if ((a > c2) == up) { keys[t] = c2; keys[ixj] = a; }
                }
            }
            __syncthreads();
        }
        #pragma unroll
        for (int r4 = 0; r4 < 4; r4++) v[r4] = keys[e0 + r4];
        warp_tail(v, e0, k);
        #pragma unroll
        for (int r4 = 0; r4 < 4; r4++) keys[e0 + r4] = v[r4];
        __syncthreads();
    }

    // ---- Precompute packed (s,e) per sorted position ----
    #pragma unroll
    for (int p = tid; p < MM; p += THR) {
        int m = (int)(keys[p] & 0xFFFFFFFFu);
        se[p] = (unsigned short)((int)rtab[m] | (((int)ctab[m] + 1) << 8));
    }
    __syncthreads();

    // ---- Greedy selection: block-parallel mask compute, <= TOPK heavy iters ----
    {
        int i = 0, cnt = 0;
        while (cnt < TOPK && i < MM - 1) {
            if ((sup[i >> 5] >> (i & 31)) & 1u) { i++; continue; }   // uniform skip
            int se0 = se[i];
            int s0 = se0 & 0xFF, eH = se0 >> 8;

            // compute IoU mask bits for all 2080 positions; ballots -> word masks
            #pragma unroll
            for (int c = 0; c < 3; c++) {
                int pos = c * 1024 + tid;
                bool mbit = false;
                if (pos < MM && pos > i) {
                    int se1 = se[pos];
                    int s1 = se1 & 0xFF, e1 = se1 >> 8;
                    int inter = min(e1, eH) - max(s1, s0);
                    int uni   = max(e1, eH) - min(s1, s0);
                    mbit = (inter > 0) && (2 * inter > uni);   // iou > 0.5 exact
                }
                unsigned mk = __ballot_sync(0xFFFFFFFFu, mbit);
                int wix = c * 32 + wv;
                if (lane == 0 && wix < NWORDS) tmpm[wix] = mk;
            }
            __syncthreads();

            // serial prefix pass over 65 words: neighbor cutoff + OR into state
            if (tid == 0) {
                int count = 0;
                for (int w = 0; w < NWORDS; w++) {
                    unsigned mk = tmpm[w];
                    int pc = __popc(mk);
                    unsigned nbm;
                    if (count >= NEIGHBOR)            nbm = 0u;
                    else if (count + pc <= NEIGHBOR)  nbm = mk;
                    else {
                        int keep = NEIGHBOR - count;
                        unsigned t2 = mk;
                        while (__popc(t2) > keep)     // drop highest set bits
                            t2 ^= (0x80000000u >> __clz(t2));
                        nbm = t2;
                    }
                    sup[w]  |= mk;
                    selb[w] |= nbm;
                    count += pc;
                }
                sup[i >> 5]  |= 1u << (i & 31);
                selb[i >> 5] |= 1u << (i & 31);
            }
            __syncthreads();
            cnt++; i++;
        }
    }
    __syncthreads();

    // ---- Word-level exclusive prefix counts (serial over 65 words, cheap) ----
    if (tid == 0) {
        int au = 0, as2 = 0;
        for (int w = 0; w < NWORDS; w++) {
            Pun[w]  = au;  au  += __popc(~sup[w]);
            Psel[w] = as2; as2 += __popc(selb[w]);
        }
        s_nunsup = au;
        s_pad    = TOTAL - as2;     // n_sel <= 85 structurally
    }
    __syncthreads();

    // ---- Parallel emit of neg/mid position lists by rank ----
    if (tid < NWORDS) {
        const int w = tid;
        const int pad = s_pad, nun = s_nunsup;
        unsigned un = ~sup[w];
        int rank = Pun[w];
        while (un) {
            int bp = __ffs(un) - 1; un &= un - 1;
            int pos = (w << 5) + bp;
            if (rank == 0) s_first = pos;
            if (rank < pad) midpos[rank] = pos;               // top-unsup padding
            int back = nun - 1 - rank;                        // reversed tail
            if (back >= 0 && back < NEGATIVE) negpos[back] = pos;
            rank++;
        }
        unsigned sl = selb[w];
        int rs = Psel[w];
        while (sl) {
            int bp = __ffs(sl) - 1; sl &= sl - 1;
            int pos = (w << 5) + bp;
            int slot = pad + rs;
            if (slot < TOTAL) midpos[slot] = pos;
            rs++;
        }
    }
    __syncthreads();
    // clip(n_unsup-1-j, 0, ...): j >= n_unsup -> unsup_idx[0] (or fill)
    if (tid < NEGATIVE && tid >= s_nunsup) negpos[tid] = s_first;
    __syncthreads();

    if (tid < KOUT) {
        int pos = (tid < NEGATIVE) ? negpos[tid] : midpos[tid - NEGATIVE];
        g_sel_m[b * KOUT + tid] = (int)(keys[pos] & 0xFFFFFFFFu);
    }
}

__global__ __launch_bounds__(128)
void gather_kernel(const float* __restrict__ map2d,
                   const float* __restrict__ offset_gt,
                   const float* __restrict__ tmap,
                   float* __restrict__ out)
{
    const int k = blockIdx.x;          // 0..3231
    const int b = k / KOUT;
    const int m = g_sel_m[k];

    // invert triangular enumeration: largest r with tri_base(r) <= m
    int lo = 0, hi = NN - 1;
    while (lo < hi) {
        int md = (lo + hi + 1) >> 1;
        if (tri_base(md) <= m) lo = md; else hi = md - 1;
    }
    const int r = lo;
    const int c = r + (m - tri_base(r));

    const size_t cell = ((size_t)b * NN + r) * NN + c;
    const float4* src = (const float4*)(map2d + cell * DD);
    float4*       dst = (float4*)(out + (size_t)k * DD);
    dst[threadIdx.x] = src[threadIdx.x];   // 128 threads * float4 = 512 floats

    if (threadIdx.x == 0) {
        out[F1 + 2 * k]     = (float)r;
        out[F1 + 2 * k + 1] = (float)(c + 1);
        out[F2 + 2 * k]     = offset_gt[cell * 2];
        out[F2 + 2 * k + 1] = offset_gt[cell * 2 + 1];
        out[F3 + k]         = tmap[cell];
    }
}

extern "C" void kernel_launch(void* const* d_in, const int* in_sizes, int n_in,
                              void* d_out, int out_size)
{
    // Inputs: score_pred, map2d_mask(bool, ignored), map2d, offset_gt, tmap
    const float* score = (const float*)d_in[0];
    int o = (n_in >= 5) ? 1 : 0;   // skip the mask input if present
    const float* map2d  = (const float*)d_in[1 + o];
    const float* offg   = (const float*)d_in[2 + o];
    const float* tm     = (const float*)d_in[3 + o];
    float* out = (float*)d_out;

    select_kernel<<<BB, THR>>>(score);
    gather_kernel<<<BK, 128>>>(map2d, offg, tm, out);
}

// round 7
// speedup vs baseline: 6.3822x; 2.0958x over previous
#include <cuda_runtime.h>
#include <cuda_bf16.h>

// Problem constants
#define NN        64
#define MM        2080          // N*(N+1)/2
#define NWORDS    65            // 2080/32
#define TOPK      5
#define NEIGHBOR  16
#define NEGATIVE  16
#define TOTAL     85
#define KOUT      101
#define BB        32
#define DD        512
#define SORTM     2048          // main sorted chunk (power of 2)
#define NEXTRA    32            // MM - SORTM
#define THRS      256           // select threads: 8 warps, 8 keys/thread

#define BK        (BB*KOUT)     // 3232
#define F1        (BK*DD)
#define F2        (F1 + BK*2)
#define F3        (F2 + BK*2)

__device__ int g_cell[BK];      // (b*NN+r)*NN+c per output row

__device__ __forceinline__ int tri_base(int r) { return r * (129 - r) / 2; }

__device__ __forceinline__ void cswap(unsigned long long& a, unsigned long long& b, bool up)
{
    if ((a > b) == up) { unsigned long long t = a; a = b; b = t; }
}

// In-register bitonic stage, J in {1,2,4}, over 8 contiguous elements e0..e0+7
template<int J, int K>
__device__ __forceinline__ void sreg(unsigned long long v[8], int e0)
{
    #pragma unroll
    for (int r = 0; r < 8; r++)
        if ((r & J) == 0) cswap(v[r], v[r + J], ((e0 + r) & K) == 0);
}

// Shuffle bitonic stage, J in {8..128}: partner lane = lane ^ (J/8)
template<int J, int K>
__device__ __forceinline__ void sshf(unsigned long long v[8], int e0)
{
    #pragma unroll
    for (int r = 0; r < 8; r++) {
        unsigned long long o = __shfl_xor_sync(0xFFFFFFFFu, v[r], J >> 3);
        int e = e0 + r;
        bool tm = (((e & J) == 0) == ((e & K) == 0));
        v[r] = ((v[r] < o) == tm) ? v[r] : o;
    }
}

// Warp-local tail of phase K (>=512): j = 128..1
template<int K>
__device__ __forceinline__ void tail8(unsigned long long v[8], int e0)
{
    sshf<128,K>(v,e0); sshf<64,K>(v,e0); sshf<32,K>(v,e0);
    sshf<16,K>(v,e0);  sshf<8,K>(v,e0);
    sreg<4,K>(v,e0);   sreg<2,K>(v,e0);  sreg<1,K>(v,e0);
}

__device__ __forceinline__ void smem_stage(unsigned long long* keys, int tid, int j, int k)
{
    #pragma unroll
    for (int t = tid; t < SORTM; t += THRS) {
        int ixj = t ^ j;
        if (ixj > t) {
            unsigned long long a = keys[t], c2 = keys[ixj];
            if ((a > c2) == ((t & k) == 0)) { keys[t] = c2; keys[ixj] = a; }
        }
    }
    __syncthreads();
}

__device__ __forceinline__ int lb(const unsigned long long* a, int n, unsigned long long key)
{
    int lo = 0, hi = n;
    while (lo < hi) { int md = (lo + hi) >> 1; if (a[md] < key) lo = md + 1; else hi = md; }
    return lo;
}

__device__ __forceinline__ unsigned long long packkey(
    const float* sp, const unsigned char* rt, const unsigned char* ct, int m)
{
    unsigned u  = __float_as_uint(sp[(int)rt[m] * NN + (int)ct[m]]);
    unsigned sa = (u & 0x80000000u) ? ~u : (u | 0x80000000u);
    return ((unsigned long long)(~sa) << 32) | (unsigned)m;   // descending score, stable
}

// nbm = lowest `NEIGHBOR-cb` set bits (earliest sorted positions); OR into state
__device__ __forceinline__ void apply_word(unsigned* sup, unsigned* selb, int w, unsigned mk, int cb)
{
    sup[w] |= mk;
    unsigned nbm = 0u;
    if (cb < NEIGHBOR) {
        int keep = NEIGHBOR - cb;
        nbm = mk;
        int pc = __popc(mk);
        while (pc > keep) { nbm ^= (0x80000000u >> __clz(nbm)); pc--; }
    }
    selb[w] |= nbm;
}

__global__ __launch_bounds__(THRS)
void select_kernel(const float* __restrict__ score_pred,
                   const float* __restrict__ offset_gt,
                   const float* __restrict__ tmap,
                   float* __restrict__ out)
{
    __shared__ unsigned long long keys[SORTM];     // main sorted
    __shared__ unsigned long long fkeys[MM];       // merged final order
    __shared__ unsigned long long extras[NEXTRA];
    __shared__ unsigned char rtab[MM], ctab[MM];
    __shared__ unsigned short se[MM];
    __shared__ unsigned int sup[NWORDS], selb[NWORDS], tmpm[NWORDS];
    __shared__ int Pun[NWORDS], Psel[NWORDS];
    __shared__ int midpos[TOTAL], negpos[NEGATIVE];
    __shared__ int s_nunsup, s_pad, s_first;

    const int b    = blockIdx.x;
    const int tid  = threadIdx.x;
    const int lane = tid & 31;
    const int wv   = tid >> 5;
    const int e0   = tid * 8;

    if (tid < NN) {
        int r = tid, base = tri_base(r);
        for (int c = r; c < NN; c++) {
            rtab[base + c - r] = (unsigned char)r;
            ctab[base + c - r] = (unsigned char)c;
        }
    }
    if (tid < NWORDS) { sup[tid] = 0u; selb[tid] = 0u; }
    if (tid < TOTAL)    midpos[tid] = MM - 1;
    if (tid < NEGATIVE) negpos[tid] = MM - 1;
    if (tid == 0) s_first = MM - 1;
    __syncthreads();

    const float* sp = score_pred + (size_t)b * NN * NN;
    unsigned long long v[8];
    #pragma unroll
    for (int r = 0; r < 8; r++) v[r] = packkey(sp, rtab, ctab, e0 + r);

    // ---- Phase A: k = 2..256 entirely warp-local (no barriers) ----
    sreg<1,2>(v,e0);
    sreg<2,4>(v,e0);  sreg<1,4>(v,e0);
    sreg<4,8>(v,e0);  sreg<2,8>(v,e0);  sreg<1,8>(v,e0);
    sshf<8,16>(v,e0); sreg<4,16>(v,e0); sreg<2,16>(v,e0); sreg<1,16>(v,e0);
    sshf<16,32>(v,e0); sshf<8,32>(v,e0);
    sreg<4,32>(v,e0);  sreg<2,32>(v,e0); sreg<1,32>(v,e0);
    sshf<32,64>(v,e0); sshf<16,64>(v,e0); sshf<8,64>(v,e0);
    sreg<4,64>(v,e0);  sreg<2,64>(v,e0);  sreg<1,64>(v,e0);
    sshf<64,128>(v,e0); sshf<32,128>(v,e0); sshf<16,128>(v,e0); sshf<8,128>(v,e0);
    sreg<4,128>(v,e0);  sreg<2,128>(v,e0);  sreg<1,128>(v,e0);
    sshf<128,256>(v,e0); sshf<64,256>(v,e0); sshf<32,256>(v,e0);
    sshf<16,256>(v,e0);  sshf<8,256>(v,e0);
    sreg<4,256>(v,e0);   sreg<2,256>(v,e0); sreg<1,256>(v,e0);

    #pragma unroll
    for (int r = 0; r < 8; r++) keys[e0 + r] = v[r];
    __syncthreads();

    // ---- k=512 ----
    smem_stage(keys, tid, 256, 512);
    #pragma unroll
    for (int r = 0; r < 8; r++) v[r] = keys[e0 + r];
    tail8<512>(v, e0);
    #pragma unroll
    for (int r = 0; r < 8; r++) keys[e0 + r] = v[r];
    __syncthreads();

    // ---- k=1024 ----
    smem_stage(keys, tid, 512, 1024);
    smem_stage(keys, tid, 256, 1024);
    #pragma unroll
    for (int r = 0; r < 8; r++) v[r] = keys[e0 + r];
    tail8<1024>(v, e0);
    #pragma unroll
    for (int r = 0; r < 8; r++) keys[e0 + r] = v[r];
    __syncthreads();

    // ---- k=2048 ----
    smem_stage(keys, tid, 1024, 2048);
    smem_stage(keys, tid,  512, 2048);
    smem_stage(keys, tid,  256, 2048);
    #pragma unroll
    for (int r = 0; r < 8; r++) v[r] = keys[e0 + r];
    tail8<2048>(v, e0);
    #pragma unroll
    for (int r = 0; r < 8; r++) keys[e0 + r] = v[r];   // keys = sorted main
    __syncthreads();

    // ---- Sort the 32 extras in warp 0 (shuffle bitonic, 1 elem/lane) ----
    if (tid < 32) {
        unsigned long long ek = packkey(sp, rtab, ctab, SORTM + tid);
        for (int kk = 2; kk <= 32; kk <<= 1)
            for (int j = kk >> 1; j >= 1; j >>= 1) {
                unsigned long long o = __shfl_xor_sync(0xFFFFFFFFu, ek, j);
                bool tm = (((lane & j) == 0) == ((lane & kk) == 0));
                ek = ((ek < o) == tm) ? ek : o;
            }
        extras[tid] = ek;
    }
    __syncthreads();

    // ---- Merge scatter: unique keys -> positions form a permutation ----
    #pragma unroll
    for (int r = 0; r < 8; r++) {
        int c = lb(extras, NEXTRA, v[r]);        // #extras < this main key
        fkeys[e0 + r + c] = v[r];
    }
    if (tid < 32) {
        unsigned long long ek = extras[tid];
        int rank = lb(keys, SORTM, ek);          // #mains < this extra key
        fkeys[rank + tid] = ek;
    }
    __syncthreads();

    // ---- Packed (s,e) per sorted position ----
    for (int p = tid; p < MM; p += THRS) {
        int m = (int)(fkeys[p] & 0xFFFFFFFFu);
        se[p] = (unsigned short)((int)rtab[m] | (((int)ctab[m] + 1) << 8));
    }
    __syncthreads();

    // ---- Greedy selection: <= TOPK heavy iterations ----
    {
        int i = 0, cnt = 0;
        while (cnt < TOPK && i < MM - 1) {
            if ((sup[i >> 5] >> (i & 31)) & 1u) { i++; continue; }
            int se0 = se[i];
            int s0 = se0 & 0xFF, eH = se0 >> 8;

            #pragma unroll
            for (int c = 0; c < 9; c++) {
                int pos = c * THRS + tid;
                bool mbit = false;
                if (pos < MM && pos > i) {
                    int se1 = se[pos];
                    int s1 = se1 & 0xFF, e1 = se1 >> 8;
                    int inter = min(e1, eH) - max(s1, s0);
                    int uni   = max(e1, eH) - min(s1, s0);
                    mbit = (inter > 0) && (2 * inter > uni);   // iou > 0.5 exact
                }
                unsigned mk = __ballot_sync(0xFFFFFFFFu, mbit);
                int wix = c * 8 + wv;
                if (lane == 0 && wix < NWORDS) tmpm[wix] = mk;
            }
            __syncthreads();

            // warp-parallel prefix over 65 words + neighbor cutoff
            if (tid < 32) {
                unsigned mk0 = tmpm[lane];
                unsigned mk1 = tmpm[lane + 32];
                unsigned mk2 = (lane == 0) ? tmpm[64] : 0u;
                int pc0 = __popc(mk0), pc1 = __popc(mk1);
                int s = pc0;
                #pragma unroll
                for (int d = 1; d < 32; d <<= 1) { int t2 = __shfl_up_sync(0xFFFFFFFFu, s, d); if (lane >= d) s += t2; }
                int pre0 = s - pc0;
                int tot0 = __shfl_sync(0xFFFFFFFFu, s, 31);
                int s2 = pc1;
                #pragma unroll
                for (int d = 1; d < 32; d <<= 1) { int t2 = __shfl_up_sync(0xFFFFFFFFu, s2, d); if (lane >= d) s2 += t2; }
                int pre1  = tot0 + s2 - pc1;
                int tot01 = tot0 + __shfl_sync(0xFFFFFFFFu, s2, 31);

                apply_word(sup, selb, lane,      mk0, pre0);
                apply_word(sup, selb, lane + 32, mk1, pre1);
                if (lane == 0) apply_word(sup, selb, 64, mk2, tot01);
                __syncwarp();
                if (lane == 0) {
                    sup[i >> 5]  |= 1u << (i & 31);
                    selb[i >> 5] |= 1u << (i & 31);
                }
            }
            __syncthreads();
            cnt++; i++;
        }
    }
    __syncthreads();

    // ---- Warp-parallel exclusive prefix counts over 65 words ----
    if (tid < 32) {
        int u0 = __popc(~sup[lane]), u1 = __popc(~sup[lane + 32]);
        int u2 = (lane == 0) ? __popc(~sup[64]) : 0;
        int s = u0;
        #pragma unroll
        for (int d = 1; d < 32; d <<= 1) { int t2 = __shfl_up_sync(0xFFFFFFFFu, s, d); if (lane >= d) s += t2; }
        Pun[lane] = s - u0;
        int tot0 = __shfl_sync(0xFFFFFFFFu, s, 31);
        int s2 = u1;
        #pragma unroll
        for (int d = 1; d < 32; d <<= 1) { int t2 = __shfl_up_sync(0xFFFFFFFFu, s2, d); if (lane >= d) s2 += t2; }
        Pun[lane + 32] = tot0 + s2 - u1;
        int totu = tot0 + __shfl_sync(0xFFFFFFFFu, s2, 31);
        if (lane == 0) { Pun[64] = totu; s_nunsup = totu + u2; }

        int v0 = __popc(selb[lane]), v1 = __popc(selb[lane + 32]);
        int v2 = (lane == 0) ? __popc(selb[64]) : 0;
        int t3 = v0;
        #pragma unroll
        for (int d = 1; d < 32; d <<= 1) { int t2 = __shfl_up_sync(0xFFFFFFFFu, t3, d); if (lane >= d) t3 += t2; }
        Psel[lane] = t3 - v0;
        int st0 = __shfl_sync(0xFFFFFFFFu, t3, 31);
        int t4 = v1;
        #pragma unroll
        for (int d = 1; d < 32; d <<= 1) { int t2 = __shfl_up_sync(0xFFFFFFFFu, t4, d); if (lane >= d) t4 += t2; }
        Psel[lane + 32] = st0 + t4 - v1;
        int tots = st0 + __shfl_sync(0xFFFFFFFFu, t4, 31);
        if (lane == 0) { Psel[64] = tots; s_pad = TOTAL - (tots + v2); }
    }
    __syncthreads();

    // ---- Parallel emit of neg/mid position lists by rank ----
    if (tid < NWORDS) {
        const int w = tid;
        const int pad = s_pad, nun = s_nunsup;
        unsigned un = ~sup[w];
        int rank = Pun[w];
        while (un) {
            int bp = __ffs(un) - 1; un &= un - 1;
            int pos = (w << 5) + bp;
            if (rank == 0) s_first = pos;
            if (rank < pad) midpos[rank] = pos;
            int back = nun - 1 - rank;
            if (back >= 0 && back < NEGATIVE) negpos[back] = pos;
            rank++;
        }
        unsigned sl = selb[w];
        int rs = Psel[w];
        while (sl) {
            int bp = __ffs(sl) - 1; sl &= sl - 1;
            int pos = (w << 5) + bp;
            int slot = pad + rs;
            if (slot < TOTAL) midpos[slot] = pos;
            rs++;
        }
    }
    __syncthreads();
    if (tid < NEGATIVE && tid >= s_nunsup) negpos[tid] = s_first;
    __syncthreads();

    // ---- Epilogue: scalar outputs + cell indices ----
    if (tid < KOUT) {
        int pos = (tid < NEGATIVE) ? negpos[tid] : midpos[tid - NEGATIVE];
        int m = (int)(fkeys[pos] & 0xFFFFFFFFu);
        int r = rtab[m], c = ctab[m];
        int k = b * KOUT + tid;
        int cell = (b * NN + r) * NN + c;
        g_cell[k] = cell;
        out[F1 + 2 * k]     = (float)r;
        out[F1 + 2 * k + 1] = (float)(c + 1);
        out[F2 + 2 * k]     = offset_gt[(size_t)cell * 2];
        out[F2 + 2 * k + 1] = offset_gt[(size_t)cell * 2 + 1];
        out[F3 + k]         = tmap[cell];
    }
}

// Pure feature copy: 202*256 threads * 8 float4 = 413696 = BK*128 exactly
__global__ __launch_bounds__(256)
void feat_copy(const float* __restrict__ map2d, float* __restrict__ out)
{
    const int base = blockIdx.x * 256 + threadIdx.x;   // 0..51711
    #pragma unroll
    for (int it = 0; it < 8; it++) {
        int i = base + it * 51712;
        int k = i >> 7, t = i & 127;
        int cell = g_cell[k];
        float4 val = ((const float4*)(map2d + (size_t)cell * DD))[t];
        ((float4*)out)[(size_t)k * 128 + t] = val;
    }
}

extern "C" void kernel_launch(void* const* d_in, const int* in_sizes, int n_in,
                              void* d_out, int out_size)
{
    // Inputs: score_pred, map2d_mask(bool, ignored), map2d, offset_gt, tmap
    const float* score = (const float*)d_in[0];
    int o = (n_in >= 5) ? 1 : 0;
    const float* map2d  = (const float*)d_in[1 + o];
    const float* offg   = (const float*)d_in[2 + o];
    const float* tm     = (const float*)d_in[3 + o];
    float* out = (float*)d_out;

    select_kernel<<<BB, THRS>>>(score, offg, tm, out);
    feat_copy<<<202, 256>>>(map2d, out);
}